// round 15
// baseline (speedup 1.0000x reference)
#include <cuda_runtime.h>
#include <cuda_fp16.h>
#include <cuda_bf16.h>
#include <cstdint>

#define TT 12
#define NN 10000
#define EE 160000
#define CAP 96   // padded CSR row capacity (deg ~ Poisson(16); P(>96) ~ 1e-40)

typedef unsigned long long u64;

__device__ __forceinline__ u64 splat2(float v) {
    u64 r; asm("mov.b64 %0,{%1,%1};" : "=l"(r) : "f"(v)); return r;
}
__device__ __forceinline__ u64 pack2(float lo, float hi) {
    u64 r; asm("mov.b64 %0,{%1,%2};" : "=l"(r) : "f"(lo), "f"(hi)); return r;
}
__device__ __forceinline__ void fma2(u64& acc, u64 a, u64 b) {
    asm("fma.rn.f32x2 %0,%1,%2,%0;" : "+l"(acc) : "l"(a), "l"(b));
}
__device__ __forceinline__ void add2(u64& acc, u64 v) {
    asm("add.rn.f32x2 %0,%0,%1;" : "+l"(acc) : "l"(v));
}
__device__ __forceinline__ float2 unpack2(u64 v) {
    float2 f; asm("mov.b64 {%0,%1},%2;" : "=f"(f.x), "=f"(f.y) : "l"(v)); return f;
}
__device__ __forceinline__ __half2 u2h2(unsigned int u) {
    return *reinterpret_cast<const __half2*>(&u);
}
__device__ __forceinline__ u64 h2u64(__half2 h) {
    float2 f = __half22float2(h);
    return pack2(f.x, f.y);
}

// ---------------- device scratch ----------------
__device__ __align__(16) __half g_h1h[NN * TT * 64];  // layer1 h, NODE-MAJOR [n][t][ch], 96 uint4/row
__device__ float   g_xs2[NN * 64];
__device__ __half  g_w1h[64 * 96];         // conv1 weights fp16, [co][K], K = tap*32+ci
__device__ __half  g_w2h[64 * 192];        // composed conv2 weights fp16, [co][K], K = tap*64+ci
__device__ float   g_S0[64];
__device__ float   g_S2[64];
__device__ u64     g_hist[NN];             // cnt in bits[40..], deg fixed-point 2^-24 in [0..40)
__device__ int     g_fill[NN];
__device__ int     g_csrc[NN * CAP];       // padded CSR
__device__ float   g_cnorm[NN * CAP];

#define FIXP 16777216.0f   // 2^24
#define FIXM 0xFFFFFFFFFFull
#define ROWQ 96            // uint4 per g_h1h node row (12*64*2B / 16B)

// ---------------- edge histogram (packed u64 atomic) ----------------
__global__ void k_hist(const int* __restrict__ ei, const float* __restrict__ ew) {
    int e = blockIdx.x * blockDim.x + threadIdx.x;
    if (e >= EE) return;
    int d = ei[EE + e];
    u64 v = ((u64)1 << 40) | (u64)(ew[e] * FIXP);
    atomicAdd(&g_hist[d], v);
}

// ---------------- weight prep ----------------
__global__ void k_compose(const float* __restrict__ w2, const float* __restrict__ gw1,
                          const float* __restrict__ gb1, const float* __restrict__ w1) {
    int idx = blockIdx.x * blockDim.x + threadIdx.x;
    if (idx < 4096) {
        int co = idx >> 6, c = idx & 63;
        const float* w2r = w2 + co * 192;
        const float* g1r = gw1 + c * 64;
        float s0 = 0.f, s1 = 0.f, s2 = 0.f;
        for (int d = 0; d < 64; d++) {
            float g = g1r[d];
            s0 += w2r[d * 3 + 0] * g;
            s1 += w2r[d * 3 + 1] * g;
            s2 += w2r[d * 3 + 2] * g;
        }
        g_w2h[co * 192 +   0 + c] = __float2half_rn(s0);
        g_w2h[co * 192 +  64 + c] = __float2half_rn(s1);
        g_w2h[co * 192 + 128 + c] = __float2half_rn(s2);
    } else if (idx < 4096 + 128) {
        int j = idx - 4096;
        int co = j & 63, which = j >> 6;
        const float* w2r = w2 + co * 192;
        float s = 0.f;
        int k = which ? 2 : 0;
        for (int d = 0; d < 64; d++) s += w2r[d * 3 + k] * gb1[d];
        if (which) g_S2[co] = s; else g_S0[co] = s;
    } else if (idx >= 4224 && idx < 4224 + 6144) {
        int j = idx - 4224;
        int co = j / 96, rem = j % 96;
        int ci = rem / 3, k = rem % 3;
        g_w1h[co * 96 + k * 32 + ci] = __float2half_rn(w1[j]);
    }
}

// ======================= fused: layer 1 (MMA conv + IN + relu) + padded-CSR scatter ========
#define L1N 8
__global__ void __launch_bounds__(32 * L1N, 3)
k_l1scat(const float* __restrict__ x, const float* __restrict__ gamma,
         const float* __restrict__ beta, const int* __restrict__ ei,
         const float* __restrict__ ew) {
    if (blockIdx.x >= 1250) {
        int e = (blockIdx.x - 1250) * 256 + threadIdx.x;
        if (e >= EE) return;
        int srcn = ei[e];
        int d = ei[EE + e];
        u64 hs = __ldg(&g_hist[srcn]);
        u64 hd = __ldg(&g_hist[d]);
        float dis_s = rsqrtf((float)(hs & FIXM) * (1.0f / FIXP) + 1.0f);
        float dis_d = rsqrtf((float)(hd & FIXM) * (1.0f / FIXP) + 1.0f);
        int pos = atomicAdd(&g_fill[d], 1);
        int idx = d * CAP + pos;
        g_csrc[idx] = srcn;
        g_cnorm[idx] = dis_s * ew[e] * dis_d;
        return;
    }
    // ---- layer 1 ----
    extern __shared__ float sm[];
    float* gms = sm;
    float* bes = gms + 64;
    unsigned int* aw = reinterpret_cast<unsigned int*>(bes + 64);  // [64][52]
    unsigned int* xr = aw + 64 * 52;                               // L1N * 14*20
    __half* hst = reinterpret_cast<__half*>(xr + L1N * 14 * 20);   // L1N * 12*64

    int tid = threadIdx.x;
    const int NT = 32 * L1N;
    for (int i = tid; i < 64; i += NT) { gms[i] = gamma[i]; bes[i] = beta[i]; }
    const unsigned int* wsrc = reinterpret_cast<const unsigned int*>(g_w1h);
    for (int i = tid; i < 64 * 48; i += NT) {
        int co = i / 48, k2 = i % 48;
        aw[co * 52 + k2] = wsrc[i];
    }
    int local = tid >> 5;
    int lane = tid & 31;
    int gid = lane >> 2;
    int tig = lane & 3;
    int n = blockIdx.x * L1N + local;
    unsigned int* xrow = xr + local * (14 * 20);
    __half* hstage = hst + local * (12 * 64);

    {
        int pair = lane & 15;
        int th = lane >> 4;
        if (lane < 16) { xrow[0 * 20 + lane] = 0u; xrow[13 * 20 + lane] = 0u; }
#pragma unroll
        for (int tt = 0; tt < 6; tt++) {
            int t = th * 6 + tt;
            float2 f = __ldg(reinterpret_cast<const float2*>(x + ((size_t)t * NN + n) * 32) + pair);
            __half2 h = __floats2half2_rn(f.x, f.y);
            xrow[(t + 1) * 20 + pair] = *reinterpret_cast<unsigned int*>(&h);
        }
    }
    __syncthreads();

    float d0[4][4], d1[4][4];
#pragma unroll
    for (int m = 0; m < 4; m++)
#pragma unroll
        for (int r = 0; r < 4; r++) { d0[m][r] = 0.f; d1[m][r] = 0.f; }

#pragma unroll
    for (int kt = 0; kt < 6; kt++) {
        int tap = kt >> 1;
        int l0 = (kt & 1) * 8;
        int tp0 = gid + tap;
        int tp1 = gid + 8 + tap; if (tp1 > 13) tp1 = 13;
        unsigned int b00 = xrow[tp0 * 20 + l0 + tig];
        unsigned int b01 = xrow[tp0 * 20 + l0 + tig + 4];
        unsigned int b10 = xrow[tp1 * 20 + l0 + tig];
        unsigned int b11 = xrow[tp1 * 20 + l0 + tig + 4];
#pragma unroll
        for (int mt = 0; mt < 4; mt++) {
            const unsigned int* ap = aw + (mt * 16 + gid) * 52 + kt * 8 + tig;
            unsigned int a0 = ap[0];
            unsigned int a1 = ap[8 * 52];
            unsigned int a2 = ap[4];
            unsigned int a3 = ap[8 * 52 + 4];
            asm volatile("mma.sync.aligned.m16n8k16.row.col.f32.f16.f16.f32 "
                "{%0,%1,%2,%3}, {%4,%5,%6,%7}, {%8,%9}, {%0,%1,%2,%3};"
                : "+f"(d0[mt][0]), "+f"(d0[mt][1]), "+f"(d0[mt][2]), "+f"(d0[mt][3])
                : "r"(a0), "r"(a1), "r"(a2), "r"(a3), "r"(b00), "r"(b01));
            asm volatile("mma.sync.aligned.m16n8k16.row.col.f32.f16.f16.f32 "
                "{%0,%1,%2,%3}, {%4,%5,%6,%7}, {%8,%9}, {%0,%1,%2,%3};"
                : "+f"(d1[mt][0]), "+f"(d1[mt][1]), "+f"(d1[mt][2]), "+f"(d1[mt][3])
                : "r"(a0), "r"(a1), "r"(a2), "r"(a3), "r"(b10), "r"(b11));
        }
    }

#pragma unroll
    for (int mt = 0; mt < 4; mt++) {
#pragma unroll
        for (int part = 0; part < 2; part++) {
            int co = mt * 16 + gid + part * 8;
            float v0 = part ? d0[mt][2] : d0[mt][0];
            float v1 = part ? d0[mt][3] : d0[mt][1];
            float v2 = part ? d1[mt][2] : d1[mt][0];
            float v3 = part ? d1[mt][3] : d1[mt][1];
            bool val2 = tig < 2;
            float s = v0 + v1 + (val2 ? v2 + v3 : 0.f);
            s += __shfl_xor_sync(0xffffffffu, s, 1);
            s += __shfl_xor_sync(0xffffffffu, s, 2);
            float mu = s * (1.0f / 12.0f);
            float e0 = v0 - mu, e1 = v1 - mu, e2 = v2 - mu, e3 = v3 - mu;
            float q = e0 * e0 + e1 * e1 + (val2 ? e2 * e2 + e3 * e3 : 0.f);
            q += __shfl_xor_sync(0xffffffffu, q, 1);
            q += __shfl_xor_sync(0xffffffffu, q, 2);
            float sc = rsqrtf(q * (1.0f / 12.0f) + 1e-5f) * gms[co];
            float bt = bes[co];
            hstage[(2 * tig) * 64 + co]     = __float2half_rn(fmaxf(e0 * sc + bt, 0.f));
            hstage[(2 * tig + 1) * 64 + co] = __float2half_rn(fmaxf(e1 * sc + bt, 0.f));
            if (val2) {
                hstage[(8 + 2 * tig) * 64 + co] = __float2half_rn(fmaxf(e2 * sc + bt, 0.f));
                hstage[(9 + 2 * tig) * 64 + co] = __float2half_rn(fmaxf(e3 * sc + bt, 0.f));
            }
        }
    }
    __syncwarp();
    {
        const uint4* hsu4 = reinterpret_cast<const uint4*>(hstage);
        uint4* outp = reinterpret_cast<uint4*>(g_h1h) + (size_t)n * ROWQ;
#pragma unroll
        for (int j = 0; j < 3; j++) outp[j * 32 + lane] = hsu4[j * 32 + lane];
    }
}

// ======================= fused: GCN aggregation (depth-2 pipelined gather) + layer2 MMA + epi ====
#define L2N 8
__global__ void __launch_bounds__(32 * L2N, 3)
k_l2fused(const float* __restrict__ gamma, const float* __restrict__ beta,
          const float* __restrict__ gw) {
    extern __shared__ float sm[];
    float* gms = sm;
    float* bes = gms + 64;
    float* s0s = bes + 64;
    float* s2s = s0s + 64;
    unsigned int* aw = reinterpret_cast<unsigned int*>(s2s + 64);  // [64][100]
    unsigned int* xr = aw + 64 * 100;                              // L2N * 14*36
    float* hbar = reinterpret_cast<float*>(xr + L2N * 14 * 36);

    int tid = threadIdx.x;
    const int NT = 32 * L2N;
    for (int i = tid; i < 64; i += NT) {
        gms[i] = gamma[i]; bes[i] = beta[i]; s0s[i] = g_S0[i]; s2s[i] = g_S2[i];
    }
    const unsigned int* wsrc = reinterpret_cast<const unsigned int*>(g_w2h);
    for (int i = tid; i < 64 * 96; i += NT) {
        int co = i / 96, k2 = i % 96;
        aw[co * 100 + k2] = wsrc[i];
    }
    __syncthreads();

    int local = tid >> 5;
    int lane = tid & 31;
    int gid = lane >> 2;
    int tig = lane & 3;
    int n = blockIdx.x * L2N + local;
    unsigned int* xrow = xr + local * (14 * 36);

    // ---- gather: rows prefetched 1 edge ahead, csr indices 2 edges ahead ----
    {
        u64 h = __ldg(&g_hist[n]);
        int cnt = (int)(h >> 40);
        float deg = (float)(h & FIXM) * (1.0f / FIXP);
        float dd2 = 1.0f / (deg + 1.0f);
        const uint4* hbase = reinterpret_cast<const uint4*>(g_h1h);
        const int q0 = lane, q1 = lane + 32, q2 = lane + 64;

        u64 acc[12];
#pragma unroll
        for (int j = 0; j < 12; j++) acc[j] = splat2(0.f);
        const __half2 z = __float2half2_rn(0.f);
        __half2 gacc[12];
#pragma unroll
        for (int j = 0; j < 12; j++) gacc[j] = z;

        const int* csr = g_csrc + n * CAP;
        const float* cnm = g_cnorm + n * CAP;
        float wc = 0.f, wn = 0.f;
        int sn = 0;
        uint4 cc0 = {0,0,0,0}, cc1 = {0,0,0,0}, cc2 = {0,0,0,0};
        if (cnt > 0) {
            int sc = __ldg(csr); wc = __ldg(cnm);
            const uint4* p = hbase + (size_t)sc * ROWQ;
            cc0 = __ldg(p + q0); cc1 = __ldg(p + q1); cc2 = __ldg(p + q2);
        }
        if (cnt > 1) { sn = __ldg(csr + 1); wn = __ldg(cnm + 1); }
        for (int i = 0; i < cnt; i++) {
            uint4 c0 = cc0, c1 = cc1, c2 = cc2;
            float w = wc;
            if (i + 1 < cnt) {
                const uint4* p = hbase + (size_t)sn * ROWQ;
                cc0 = __ldg(p + q0); cc1 = __ldg(p + q1); cc2 = __ldg(p + q2);
                wc = wn;
                if (i + 2 < cnt) { sn = __ldg(csr + i + 2); wn = __ldg(cnm + i + 2); }
            }
            __half2 wh = __float2half2_rn(w);
            gacc[0] = __hfma2(u2h2(c0.x), wh, gacc[0]);
            gacc[1] = __hfma2(u2h2(c0.y), wh, gacc[1]);
            gacc[2] = __hfma2(u2h2(c0.z), wh, gacc[2]);
            gacc[3] = __hfma2(u2h2(c0.w), wh, gacc[3]);
            gacc[4] = __hfma2(u2h2(c1.x), wh, gacc[4]);
            gacc[5] = __hfma2(u2h2(c1.y), wh, gacc[5]);
            gacc[6] = __hfma2(u2h2(c1.z), wh, gacc[6]);
            gacc[7] = __hfma2(u2h2(c1.w), wh, gacc[7]);
            gacc[8] = __hfma2(u2h2(c2.x), wh, gacc[8]);
            gacc[9] = __hfma2(u2h2(c2.y), wh, gacc[9]);
            gacc[10] = __hfma2(u2h2(c2.z), wh, gacc[10]);
            gacc[11] = __hfma2(u2h2(c2.w), wh, gacc[11]);
            if ((i & 3) == 3) {
#pragma unroll
                for (int j = 0; j < 12; j++) { add2(acc[j], h2u64(gacc[j])); gacc[j] = z; }
            }
        }
#pragma unroll
        for (int j = 0; j < 12; j++) add2(acc[j], h2u64(gacc[j]));

        // self-loop term in f32
        {
            const uint4* pn = hbase + (size_t)n * ROWQ;
            uint4 s0 = __ldg(pn + q0), s1 = __ldg(pn + q1), s2 = __ldg(pn + q2);
            u64 D2 = splat2(dd2);
            fma2(acc[0], D2, h2u64(u2h2(s0.x)));
            fma2(acc[1], D2, h2u64(u2h2(s0.y)));
            fma2(acc[2], D2, h2u64(u2h2(s0.z)));
            fma2(acc[3], D2, h2u64(u2h2(s0.w)));
            fma2(acc[4], D2, h2u64(u2h2(s1.x)));
            fma2(acc[5], D2, h2u64(u2h2(s1.y)));
            fma2(acc[6], D2, h2u64(u2h2(s1.z)));
            fma2(acc[7], D2, h2u64(u2h2(s1.w)));
            fma2(acc[8], D2, h2u64(u2h2(s2.x)));
            fma2(acc[9], D2, h2u64(u2h2(s2.y)));
            fma2(acc[10], D2, h2u64(u2h2(s2.z)));
            fma2(acc[11], D2, h2u64(u2h2(s2.w)));
        }

        xrow[0 * 36 + lane] = 0u;
        xrow[13 * 36 + lane] = 0u;
#pragma unroll
        for (int k = 0; k < 3; k++) {
            int q = lane + 32 * k;
            int t = q >> 3;
            int col0 = (q & 7) * 4;
            uint4 o;
            float2 f;
            __half2 hv;
            f = unpack2(acc[4 * k + 0]); hv = __floats2half2_rn(f.x, f.y); o.x = *reinterpret_cast<unsigned int*>(&hv);
            f = unpack2(acc[4 * k + 1]); hv = __floats2half2_rn(f.x, f.y); o.y = *reinterpret_cast<unsigned int*>(&hv);
            f = unpack2(acc[4 * k + 2]); hv = __floats2half2_rn(f.x, f.y); o.z = *reinterpret_cast<unsigned int*>(&hv);
            f = unpack2(acc[4 * k + 3]); hv = __floats2half2_rn(f.x, f.y); o.w = *reinterpret_cast<unsigned int*>(&hv);
            *reinterpret_cast<uint4*>(xrow + (t + 1) * 36 + col0) = o;
        }
    }
    __syncwarp();

    float d0[4][4], d1[4][4];
#pragma unroll
    for (int m = 0; m < 4; m++)
#pragma unroll
        for (int r = 0; r < 4; r++) { d0[m][r] = 0.f; d1[m][r] = 0.f; }

#pragma unroll
    for (int kt = 0; kt < 12; kt++) {
        int tap = kt >> 2;
        int l0 = (kt & 3) * 8;
        int tp0 = gid + tap;
        int tp1 = gid + 8 + tap; if (tp1 > 13) tp1 = 13;
        unsigned int b00 = xrow[tp0 * 36 + l0 + tig];
        unsigned int b01 = xrow[tp0 * 36 + l0 + tig + 4];
        unsigned int b10 = xrow[tp1 * 36 + l0 + tig];
        unsigned int b11 = xrow[tp1 * 36 + l0 + tig + 4];
#pragma unroll
        for (int mt = 0; mt < 4; mt++) {
            const unsigned int* ap = aw + (mt * 16 + gid) * 100 + kt * 8 + tig;
            unsigned int a0 = ap[0];
            unsigned int a1 = ap[8 * 100];
            unsigned int a2 = ap[4];
            unsigned int a3 = ap[8 * 100 + 4];
            asm volatile("mma.sync.aligned.m16n8k16.row.col.f32.f16.f16.f32 "
                "{%0,%1,%2,%3}, {%4,%5,%6,%7}, {%8,%9}, {%0,%1,%2,%3};"
                : "+f"(d0[mt][0]), "+f"(d0[mt][1]), "+f"(d0[mt][2]), "+f"(d0[mt][3])
                : "r"(a0), "r"(a1), "r"(a2), "r"(a3), "r"(b00), "r"(b01));
            asm volatile("mma.sync.aligned.m16n8k16.row.col.f32.f16.f16.f32 "
                "{%0,%1,%2,%3}, {%4,%5,%6,%7}, {%8,%9}, {%0,%1,%2,%3};"
                : "+f"(d1[mt][0]), "+f"(d1[mt][1]), "+f"(d1[mt][2]), "+f"(d1[mt][3])
                : "r"(a0), "r"(a1), "r"(a2), "r"(a3), "r"(b10), "r"(b11));
        }
    }

#pragma unroll
    for (int mt = 0; mt < 4; mt++) {
#pragma unroll
        for (int part = 0; part < 2; part++) {
            int co = mt * 16 + gid + part * 8;
            float v0 = part ? d0[mt][2] : d0[mt][0];
            float v1 = part ? d0[mt][3] : d0[mt][1];
            float v2 = part ? d1[mt][2] : d1[mt][0];
            float v3 = part ? d1[mt][3] : d1[mt][1];
            if (tig == 0) v0 -= s0s[co];
            if (tig == 1) v3 -= s2s[co];
            bool val2 = tig < 2;
            float s = v0 + v1 + (val2 ? v2 + v3 : 0.f);
            s += __shfl_xor_sync(0xffffffffu, s, 1);
            s += __shfl_xor_sync(0xffffffffu, s, 2);
            float mu = s * (1.0f / 12.0f);
            float e0 = v0 - mu, e1 = v1 - mu, e2 = v2 - mu, e3 = v3 - mu;
            float q = e0 * e0 + e1 * e1 + (val2 ? e2 * e2 + e3 * e3 : 0.f);
            q += __shfl_xor_sync(0xffffffffu, q, 1);
            q += __shfl_xor_sync(0xffffffffu, q, 2);
            float sc = rsqrtf(q * (1.0f / 12.0f) + 1e-5f) * gms[co];
            float bt = bes[co];
            float r = fmaxf(e0 * sc + bt, 0.f) + fmaxf(e1 * sc + bt, 0.f)
                    + (val2 ? fmaxf(e2 * sc + bt, 0.f) + fmaxf(e3 * sc + bt, 0.f) : 0.f);
            r += __shfl_xor_sync(0xffffffffu, r, 1);
            r += __shfl_xor_sync(0xffffffffu, r, 2);
            if (tig == 0) hbar[local * 64 + co] = r * (1.0f / 12.0f);
        }
    }
    __syncwarp();

    {
        const float4* hl4 = reinterpret_cast<const float4*>(hbar + local * 64);
        const float2* gp = reinterpret_cast<const float2*>(gw) + lane;
        u64 oacc = splat2(0.f);
        for (int c4 = 0; c4 < 16; c4++) {
            float4 hc = hl4[c4];
            int c = c4 * 4;
            float2 g0 = __ldg(gp + (c + 0) * 32);
            float2 g1 = __ldg(gp + (c + 1) * 32);
            float2 g2 = __ldg(gp + (c + 2) * 32);
            float2 g3 = __ldg(gp + (c + 3) * 32);
            fma2(oacc, splat2(hc.x), pack2(g0.x, g0.y));
            fma2(oacc, splat2(hc.y), pack2(g1.x, g1.y));
            fma2(oacc, splat2(hc.z), pack2(g2.x, g2.y));
            fma2(oacc, splat2(hc.w), pack2(g3.x, g3.y));
        }
        float2 o = unpack2(oacc);
        *reinterpret_cast<float2*>(g_xs2 + (size_t)n * 64 + 2 * lane) = o;
    }
}

// ---------------- layer 2 aggregation + output linear + scratch re-zero ----------------
__global__ void k_agg2_out(const float* __restrict__ gb, const float* __restrict__ ow,
                           const float* __restrict__ ob, float* __restrict__ out) {
    __shared__ float ows[64 * 32];
    __shared__ float am[8][64];
    int tid = threadIdx.x;
    for (int i = tid; i < 64 * 32; i += 256) ows[i] = ow[i];
    __syncthreads();
    int wslot = tid >> 5;
    int lane = tid & 31;
    int n = blockIdx.x * 8 + wslot;
    if (n >= NN) return;
    u64 h = __ldg(&g_hist[n]);
    int cnt = (int)(h >> 40);
    float deg = (float)(h & FIXM) * (1.0f / FIXP);
    float d2 = 1.0f / (deg + 1.0f);
    if (lane == 0) { g_hist[n] = 0ull; g_fill[n] = 0; }
    const int* csr = g_csrc + n * CAP;
    const float* cnm = g_cnorm + n * CAP;
    float a0 = 0.f, a1 = 0.f;
    // depth-2 pipelined gather
    float wc = 0.f, wn = 0.f;
    int sn = 0;
    float2 fc = make_float2(0.f, 0.f);
    if (cnt > 0) {
        int sc = __ldg(csr); wc = __ldg(cnm);
        fc = __ldg(reinterpret_cast<const float2*>(g_xs2 + (size_t)sc * 64) + lane);
    }
    if (cnt > 1) { sn = __ldg(csr + 1); wn = __ldg(cnm + 1); }
    for (int i = 0; i < cnt; i++) {
        float2 f = fc;
        float w = wc;
        if (i + 1 < cnt) {
            fc = __ldg(reinterpret_cast<const float2*>(g_xs2 + (size_t)sn * 64) + lane);
            wc = wn;
            if (i + 2 < cnt) { sn = __ldg(csr + i + 2); wn = __ldg(cnm + i + 2); }
        }
        a0 += w * f.x;
        a1 += w * f.y;
    }
    float2 pn = *(reinterpret_cast<const float2*>(g_xs2 + (size_t)n * 64) + lane);
    float2 gb2v = *(reinterpret_cast<const float2*>(gb) + lane);
    a0 += d2 * pn.x + gb2v.x;
    a1 += d2 * pn.y + gb2v.y;
    am[wslot][2 * lane] = a0;
    am[wslot][2 * lane + 1] = a1;
    __syncwarp();
    float s = ob[lane];
    const float* amr = am[wslot];
#pragma unroll 8
    for (int c = 0; c < 64; c++) s += amr[c] * ows[c * 32 + lane];
    out[(size_t)n * 32 + lane] = s;
}

// ---------------- launch ----------------
extern "C" void kernel_launch(void* const* d_in, const int* in_sizes, int n_in,
                              void* d_out, int out_size) {
    const float* x    = (const float*)d_in[0];
    const int*   ei   = (const int*)d_in[1];
    const float* ew   = (const float*)d_in[2];
    const float* cw1  = (const float*)d_in[3];
    const float* ga1  = (const float*)d_in[5];
    const float* be1  = (const float*)d_in[6];
    const float* gw1  = (const float*)d_in[7];
    const float* gb1  = (const float*)d_in[8];
    const float* cw2  = (const float*)d_in[9];
    const float* ga2  = (const float*)d_in[11];
    const float* be2  = (const float*)d_in[12];
    const float* gw2  = (const float*)d_in[13];
    const float* gb2  = (const float*)d_in[14];
    const float* ow   = (const float*)d_in[15];
    const float* ob   = (const float*)d_in[16];
    float* out = (float*)d_out;

    const int smem1 = (128 + 64 * 52 + 8 * 14 * 20 + 8 * 12 * 32) * 4;    // ~34.3KB
    const int smem2 = (256 + 64 * 100 + L2N * 14 * 36 + L2N * 64) * 4;    // ~44.8KB
    static bool attr_set = false;
    if (!attr_set) {
        cudaFuncSetAttribute(k_l1scat, cudaFuncAttributeMaxDynamicSharedMemorySize, smem1);
        cudaFuncSetAttribute(k_l2fused, cudaFuncAttributeMaxDynamicSharedMemorySize, smem2);
        attr_set = true;
    }

    // 5 launches; k_l2fused at profile slot 4
    k_hist<<<(EE + 255) / 256, 256>>>(ei, ew);
    k_compose<<<41, 256>>>(cw2, gw1, gb1, cw1);
    k_l1scat<<<1250 + 625, 256, smem1>>>(x, ga1, be1, ei, ew);
    k_l2fused<<<(NN + L2N - 1) / L2N, 32 * L2N, smem2>>>(ga2, be2, gw2);
    k_agg2_out<<<(NN + 7) / 8, 256>>>(gb2, ow, ob, out);
}

// round 16
// speedup vs baseline: 1.0447x; 1.0447x over previous
#include <cuda_runtime.h>
#include <cuda_fp16.h>
#include <cuda_bf16.h>
#include <cstdint>

#define TT 12
#define NN 10000
#define EE 160000
#define CAP 96   // padded CSR row capacity (deg ~ Poisson(16); P(>96) ~ 1e-40)

typedef unsigned long long u64;

__device__ __forceinline__ u64 splat2(float v) {
    u64 r; asm("mov.b64 %0,{%1,%1};" : "=l"(r) : "f"(v)); return r;
}
__device__ __forceinline__ u64 pack2(float lo, float hi) {
    u64 r; asm("mov.b64 %0,{%1,%2};" : "=l"(r) : "f"(lo), "f"(hi)); return r;
}
__device__ __forceinline__ void fma2(u64& acc, u64 a, u64 b) {
    asm("fma.rn.f32x2 %0,%1,%2,%0;" : "+l"(acc) : "l"(a), "l"(b));
}
__device__ __forceinline__ void add2(u64& acc, u64 v) {
    asm("add.rn.f32x2 %0,%0,%1;" : "+l"(acc) : "l"(v));
}
__device__ __forceinline__ float2 unpack2(u64 v) {
    float2 f; asm("mov.b64 {%0,%1},%2;" : "=f"(f.x), "=f"(f.y) : "l"(v)); return f;
}
__device__ __forceinline__ __half2 u2h2(unsigned int u) {
    return *reinterpret_cast<const __half2*>(&u);
}
__device__ __forceinline__ u64 h2u64(__half2 h) {
    float2 f = __half22float2(h);
    return pack2(f.x, f.y);
}

// ---------------- device scratch ----------------
__device__ __align__(16) __half g_h1h[NN * TT * 64];  // layer1 h, NODE-MAJOR [n][t][ch], 96 uint4/row
__device__ float   g_xs2[NN * 64];
__device__ __half  g_w1h[64 * 96];         // conv1 weights fp16, [co][K], K = tap*32+ci
__device__ __half  g_w2h[64 * 192];        // composed conv2 weights fp16, [co][K], K = tap*64+ci
__device__ float   g_S0[64];
__device__ float   g_S2[64];
__device__ u64     g_hist[NN];             // cnt in bits[40..], deg fixed-point 2^-24 in [0..40)
__device__ int     g_fill[NN];
__device__ int     g_csrc[NN * CAP];       // padded CSR
__device__ float   g_cnorm[NN * CAP];

#define FIXP 16777216.0f   // 2^24
#define FIXM 0xFFFFFFFFFFull
#define ROWQ 96            // uint4 per g_h1h node row (12*64*2B / 16B)

// ======== fused: edge histogram (blocks [0,625)) + weight prep (blocks [625,666)) ========
__global__ void k_histcompose(const int* __restrict__ ei, const float* __restrict__ ew,
                              const float* __restrict__ w2, const float* __restrict__ gw1,
                              const float* __restrict__ gb1, const float* __restrict__ w1) {
    if (blockIdx.x < 625) {
        int e = blockIdx.x * 256 + threadIdx.x;
        if (e >= EE) return;
        int d = ei[EE + e];
        u64 v = ((u64)1 << 40) | (u64)(ew[e] * FIXP);
        atomicAdd(&g_hist[d], v);
        return;
    }
    int idx = (blockIdx.x - 625) * 256 + threadIdx.x;
    if (idx < 4096) {
        int co = idx >> 6, c = idx & 63;
        const float* w2r = w2 + co * 192;
        const float* g1r = gw1 + c * 64;
        float s0 = 0.f, s1 = 0.f, s2 = 0.f;
        for (int d = 0; d < 64; d++) {
            float g = g1r[d];
            s0 += w2r[d * 3 + 0] * g;
            s1 += w2r[d * 3 + 1] * g;
            s2 += w2r[d * 3 + 2] * g;
        }
        g_w2h[co * 192 +   0 + c] = __float2half_rn(s0);
        g_w2h[co * 192 +  64 + c] = __float2half_rn(s1);
        g_w2h[co * 192 + 128 + c] = __float2half_rn(s2);
    } else if (idx < 4096 + 128) {
        int j = idx - 4096;
        int co = j & 63, which = j >> 6;
        const float* w2r = w2 + co * 192;
        float s = 0.f;
        int k = which ? 2 : 0;
        for (int d = 0; d < 64; d++) s += w2r[d * 3 + k] * gb1[d];
        if (which) g_S2[co] = s; else g_S0[co] = s;
    } else if (idx >= 4224 && idx < 4224 + 6144) {
        int j = idx - 4224;
        int co = j / 96, rem = j % 96;
        int ci = rem / 3, k = rem % 3;
        g_w1h[co * 96 + k * 32 + ci] = __float2half_rn(w1[j]);
    }
}

// ======================= fused: layer 1 (MMA conv + IN + relu) + padded-CSR scatter ========
#define L1N 8
__global__ void __launch_bounds__(32 * L1N, 3)
k_l1scat(const float* __restrict__ x, const float* __restrict__ gamma,
         const float* __restrict__ beta, const int* __restrict__ ei,
         const float* __restrict__ ew) {
    if (blockIdx.x >= 1250) {
        int e = (blockIdx.x - 1250) * 256 + threadIdx.x;
        if (e >= EE) return;
        int srcn = ei[e];
        int d = ei[EE + e];
        u64 hs = __ldg(&g_hist[srcn]);
        u64 hd = __ldg(&g_hist[d]);
        float dis_s = rsqrtf((float)(hs & FIXM) * (1.0f / FIXP) + 1.0f);
        float dis_d = rsqrtf((float)(hd & FIXM) * (1.0f / FIXP) + 1.0f);
        int pos = atomicAdd(&g_fill[d], 1);
        int idx = d * CAP + pos;
        g_csrc[idx] = srcn;
        g_cnorm[idx] = dis_s * ew[e] * dis_d;
        return;
    }
    // ---- layer 1 ----
    extern __shared__ float sm[];
    float* gms = sm;
    float* bes = gms + 64;
    unsigned int* aw = reinterpret_cast<unsigned int*>(bes + 64);  // [64][52]
    unsigned int* xr = aw + 64 * 52;                               // L1N * 14*20
    __half* hst = reinterpret_cast<__half*>(xr + L1N * 14 * 20);   // L1N * 12*64

    int tid = threadIdx.x;
    const int NT = 32 * L1N;
    for (int i = tid; i < 64; i += NT) { gms[i] = gamma[i]; bes[i] = beta[i]; }
    const unsigned int* wsrc = reinterpret_cast<const unsigned int*>(g_w1h);
    for (int i = tid; i < 64 * 48; i += NT) {
        int co = i / 48, k2 = i % 48;
        aw[co * 52 + k2] = wsrc[i];
    }
    int local = tid >> 5;
    int lane = tid & 31;
    int gid = lane >> 2;
    int tig = lane & 3;
    int n = blockIdx.x * L1N + local;
    unsigned int* xrow = xr + local * (14 * 20);
    __half* hstage = hst + local * (12 * 64);

    {
        int pair = lane & 15;
        int th = lane >> 4;
        if (lane < 16) { xrow[0 * 20 + lane] = 0u; xrow[13 * 20 + lane] = 0u; }
#pragma unroll
        for (int tt = 0; tt < 6; tt++) {
            int t = th * 6 + tt;
            float2 f = __ldg(reinterpret_cast<const float2*>(x + ((size_t)t * NN + n) * 32) + pair);
            __half2 h = __floats2half2_rn(f.x, f.y);
            xrow[(t + 1) * 20 + pair] = *reinterpret_cast<unsigned int*>(&h);
        }
    }
    __syncthreads();

    float d0[4][4], d1[4][4];
#pragma unroll
    for (int m = 0; m < 4; m++)
#pragma unroll
        for (int r = 0; r < 4; r++) { d0[m][r] = 0.f; d1[m][r] = 0.f; }

#pragma unroll
    for (int kt = 0; kt < 6; kt++) {
        int tap = kt >> 1;
        int l0 = (kt & 1) * 8;
        int tp0 = gid + tap;
        int tp1 = gid + 8 + tap; if (tp1 > 13) tp1 = 13;
        unsigned int b00 = xrow[tp0 * 20 + l0 + tig];
        unsigned int b01 = xrow[tp0 * 20 + l0 + tig + 4];
        unsigned int b10 = xrow[tp1 * 20 + l0 + tig];
        unsigned int b11 = xrow[tp1 * 20 + l0 + tig + 4];
#pragma unroll
        for (int mt = 0; mt < 4; mt++) {
            const unsigned int* ap = aw + (mt * 16 + gid) * 52 + kt * 8 + tig;
            unsigned int a0 = ap[0];
            unsigned int a1 = ap[8 * 52];
            unsigned int a2 = ap[4];
            unsigned int a3 = ap[8 * 52 + 4];
            asm volatile("mma.sync.aligned.m16n8k16.row.col.f32.f16.f16.f32 "
                "{%0,%1,%2,%3}, {%4,%5,%6,%7}, {%8,%9}, {%0,%1,%2,%3};"
                : "+f"(d0[mt][0]), "+f"(d0[mt][1]), "+f"(d0[mt][2]), "+f"(d0[mt][3])
                : "r"(a0), "r"(a1), "r"(a2), "r"(a3), "r"(b00), "r"(b01));
            asm volatile("mma.sync.aligned.m16n8k16.row.col.f32.f16.f16.f32 "
                "{%0,%1,%2,%3}, {%4,%5,%6,%7}, {%8,%9}, {%0,%1,%2,%3};"
                : "+f"(d1[mt][0]), "+f"(d1[mt][1]), "+f"(d1[mt][2]), "+f"(d1[mt][3])
                : "r"(a0), "r"(a1), "r"(a2), "r"(a3), "r"(b10), "r"(b11));
        }
    }

#pragma unroll
    for (int mt = 0; mt < 4; mt++) {
#pragma unroll
        for (int part = 0; part < 2; part++) {
            int co = mt * 16 + gid + part * 8;
            float v0 = part ? d0[mt][2] : d0[mt][0];
            float v1 = part ? d0[mt][3] : d0[mt][1];
            float v2 = part ? d1[mt][2] : d1[mt][0];
            float v3 = part ? d1[mt][3] : d1[mt][1];
            bool val2 = tig < 2;
            float s = v0 + v1 + (val2 ? v2 + v3 : 0.f);
            s += __shfl_xor_sync(0xffffffffu, s, 1);
            s += __shfl_xor_sync(0xffffffffu, s, 2);
            float mu = s * (1.0f / 12.0f);
            float e0 = v0 - mu, e1 = v1 - mu, e2 = v2 - mu, e3 = v3 - mu;
            float q = e0 * e0 + e1 * e1 + (val2 ? e2 * e2 + e3 * e3 : 0.f);
            q += __shfl_xor_sync(0xffffffffu, q, 1);
            q += __shfl_xor_sync(0xffffffffu, q, 2);
            float sc = rsqrtf(q * (1.0f / 12.0f) + 1e-5f) * gms[co];
            float bt = bes[co];
            hstage[(2 * tig) * 64 + co]     = __float2half_rn(fmaxf(e0 * sc + bt, 0.f));
            hstage[(2 * tig + 1) * 64 + co] = __float2half_rn(fmaxf(e1 * sc + bt, 0.f));
            if (val2) {
                hstage[(8 + 2 * tig) * 64 + co] = __float2half_rn(fmaxf(e2 * sc + bt, 0.f));
                hstage[(9 + 2 * tig) * 64 + co] = __float2half_rn(fmaxf(e3 * sc + bt, 0.f));
            }
        }
    }
    __syncwarp();
    {
        const uint4* hsu4 = reinterpret_cast<const uint4*>(hstage);
        uint4* outp = reinterpret_cast<uint4*>(g_h1h) + (size_t)n * ROWQ;
#pragma unroll
        for (int j = 0; j < 3; j++) outp[j * 32 + lane] = hsu4[j * 32 + lane];
    }
}

// ======================= fused: GCN aggregation (chunked uint4 gather) + layer2 MMA + epi ====
#define L2N 8
__global__ void __launch_bounds__(32 * L2N, 3)
k_l2fused(const float* __restrict__ gamma, const float* __restrict__ beta,
          const float* __restrict__ gw) {
    extern __shared__ float sm[];
    float* gms = sm;
    float* bes = gms + 64;
    float* s0s = bes + 64;
    float* s2s = s0s + 64;
    unsigned int* aw = reinterpret_cast<unsigned int*>(s2s + 64);  // [64][100]
    unsigned int* xr = aw + 64 * 100;                              // L2N * 14*36
    float* hbar = reinterpret_cast<float*>(xr + L2N * 14 * 36);

    int tid = threadIdx.x;
    const int NT = 32 * L2N;
    for (int i = tid; i < 64; i += NT) {
        gms[i] = gamma[i]; bes[i] = beta[i]; s0s[i] = g_S0[i]; s2s[i] = g_S2[i];
    }
    const unsigned int* wsrc = reinterpret_cast<const unsigned int*>(g_w2h);
    for (int i = tid; i < 64 * 96; i += NT) {
        int co = i / 96, k2 = i % 96;
        aw[co * 100 + k2] = wsrc[i];
    }
    __syncthreads();

    int local = tid >> 5;
    int lane = tid & 31;
    int gid = lane >> 2;
    int tig = lane & 3;
    int n = blockIdx.x * L2N + local;
    unsigned int* xrow = xr + local * (14 * 36);

    // ---- in-warp gather: lane owns 3 16B chunks q = lane + 32k of the 1536B node row ----
    {
        u64 h = __ldg(&g_hist[n]);
        int cnt = (int)(h >> 40);
        float deg = (float)(h & FIXM) * (1.0f / FIXP);
        float dd2 = 1.0f / (deg + 1.0f);
        const uint4* hbase = reinterpret_cast<const uint4*>(g_h1h);
        const int q0 = lane, q1 = lane + 32, q2 = lane + 64;

        // issue self-loop row loads early (independent of edge loop)
        const uint4* pnrow = hbase + (size_t)n * ROWQ;
        uint4 sl0 = __ldg(pnrow + q0), sl1 = __ldg(pnrow + q1), sl2 = __ldg(pnrow + q2);

        u64 acc[12];
#pragma unroll
        for (int j = 0; j < 12; j++) acc[j] = splat2(0.f);
        const __half2 z = __float2half2_rn(0.f);
        __half2 gacc[12];
#pragma unroll
        for (int j = 0; j < 12; j++) gacc[j] = z;

        const int* csr = g_csrc + n * CAP;
        const float* cnm = g_cnorm + n * CAP;
        float wN = 0.f;
        uint4 c0N = {0,0,0,0}, c1N = {0,0,0,0}, c2N = {0,0,0,0};
        if (cnt > 0) {
            int s0 = __ldg(csr); wN = __ldg(cnm);
            const uint4* p = hbase + (size_t)s0 * ROWQ;
            c0N = __ldg(p + q0); c1N = __ldg(p + q1); c2N = __ldg(p + q2);
        }
        for (int i = 0; i < cnt; i++) {
            uint4 c0 = c0N, c1 = c1N, c2 = c2N;
            float w = wN;
            if (i + 1 < cnt) {
                int s1 = __ldg(csr + i + 1); wN = __ldg(cnm + i + 1);
                const uint4* p = hbase + (size_t)s1 * ROWQ;
                c0N = __ldg(p + q0); c1N = __ldg(p + q1); c2N = __ldg(p + q2);
            }
            __half2 wh = __float2half2_rn(w);
            gacc[0] = __hfma2(u2h2(c0.x), wh, gacc[0]);
            gacc[1] = __hfma2(u2h2(c0.y), wh, gacc[1]);
            gacc[2] = __hfma2(u2h2(c0.z), wh, gacc[2]);
            gacc[3] = __hfma2(u2h2(c0.w), wh, gacc[3]);
            gacc[4] = __hfma2(u2h2(c1.x), wh, gacc[4]);
            gacc[5] = __hfma2(u2h2(c1.y), wh, gacc[5]);
            gacc[6] = __hfma2(u2h2(c1.z), wh, gacc[6]);
            gacc[7] = __hfma2(u2h2(c1.w), wh, gacc[7]);
            gacc[8] = __hfma2(u2h2(c2.x), wh, gacc[8]);
            gacc[9] = __hfma2(u2h2(c2.y), wh, gacc[9]);
            gacc[10] = __hfma2(u2h2(c2.z), wh, gacc[10]);
            gacc[11] = __hfma2(u2h2(c2.w), wh, gacc[11]);
            if ((i & 3) == 3) {   // fold fp16 group into f32 accumulators
#pragma unroll
                for (int j = 0; j < 12; j++) { add2(acc[j], h2u64(gacc[j])); gacc[j] = z; }
            }
        }
#pragma unroll
        for (int j = 0; j < 12; j++) add2(acc[j], h2u64(gacc[j]));   // leftover fold

        // self-loop term in f32 (rows already loaded)
        {
            u64 D2 = splat2(dd2);
            fma2(acc[0], D2, h2u64(u2h2(sl0.x)));
            fma2(acc[1], D2, h2u64(u2h2(sl0.y)));
            fma2(acc[2], D2, h2u64(u2h2(sl0.z)));
            fma2(acc[3], D2, h2u64(u2h2(sl0.w)));
            fma2(acc[4], D2, h2u64(u2h2(sl1.x)));
            fma2(acc[5], D2, h2u64(u2h2(sl1.y)));
            fma2(acc[6], D2, h2u64(u2h2(sl1.z)));
            fma2(acc[7], D2, h2u64(u2h2(sl1.w)));
            fma2(acc[8], D2, h2u64(u2h2(sl2.x)));
            fma2(acc[9], D2, h2u64(u2h2(sl2.y)));
            fma2(acc[10], D2, h2u64(u2h2(sl2.z)));
            fma2(acc[11], D2, h2u64(u2h2(sl2.w)));
        }

        // zero pads, write chunks into xrow (STS.128)
        xrow[0 * 36 + lane] = 0u;
        xrow[13 * 36 + lane] = 0u;
#pragma unroll
        for (int k = 0; k < 3; k++) {
            int q = lane + 32 * k;
            int t = q >> 3;
            int col0 = (q & 7) * 4;
            uint4 o;
            float2 f;
            __half2 hv;
            f = unpack2(acc[4 * k + 0]); hv = __floats2half2_rn(f.x, f.y); o.x = *reinterpret_cast<unsigned int*>(&hv);
            f = unpack2(acc[4 * k + 1]); hv = __floats2half2_rn(f.x, f.y); o.y = *reinterpret_cast<unsigned int*>(&hv);
            f = unpack2(acc[4 * k + 2]); hv = __floats2half2_rn(f.x, f.y); o.z = *reinterpret_cast<unsigned int*>(&hv);
            f = unpack2(acc[4 * k + 3]); hv = __floats2half2_rn(f.x, f.y); o.w = *reinterpret_cast<unsigned int*>(&hv);
            *reinterpret_cast<uint4*>(xrow + (t + 1) * 36 + col0) = o;
        }
    }
    __syncwarp();

    float d0[4][4], d1[4][4];
#pragma unroll
    for (int m = 0; m < 4; m++)
#pragma unroll
        for (int r = 0; r < 4; r++) { d0[m][r] = 0.f; d1[m][r] = 0.f; }

#pragma unroll
    for (int kt = 0; kt < 12; kt++) {
        int tap = kt >> 2;
        int l0 = (kt & 3) * 8;
        int tp0 = gid + tap;
        int tp1 = gid + 8 + tap; if (tp1 > 13) tp1 = 13;
        unsigned int b00 = xrow[tp0 * 36 + l0 + tig];
        unsigned int b01 = xrow[tp0 * 36 + l0 + tig + 4];
        unsigned int b10 = xrow[tp1 * 36 + l0 + tig];
        unsigned int b11 = xrow[tp1 * 36 + l0 + tig + 4];
#pragma unroll
        for (int mt = 0; mt < 4; mt++) {
            const unsigned int* ap = aw + (mt * 16 + gid) * 100 + kt * 8 + tig;
            unsigned int a0 = ap[0];
            unsigned int a1 = ap[8 * 100];
            unsigned int a2 = ap[4];
            unsigned int a3 = ap[8 * 100 + 4];
            asm volatile("mma.sync.aligned.m16n8k16.row.col.f32.f16.f16.f32 "
                "{%0,%1,%2,%3}, {%4,%5,%6,%7}, {%8,%9}, {%0,%1,%2,%3};"
                : "+f"(d0[mt][0]), "+f"(d0[mt][1]), "+f"(d0[mt][2]), "+f"(d0[mt][3])
                : "r"(a0), "r"(a1), "r"(a2), "r"(a3), "r"(b00), "r"(b01));
            asm volatile("mma.sync.aligned.m16n8k16.row.col.f32.f16.f16.f32 "
                "{%0,%1,%2,%3}, {%4,%5,%6,%7}, {%8,%9}, {%0,%1,%2,%3};"
                : "+f"(d1[mt][0]), "+f"(d1[mt][1]), "+f"(d1[mt][2]), "+f"(d1[mt][3])
                : "r"(a0), "r"(a1), "r"(a2), "r"(a3), "r"(b10), "r"(b11));
        }
    }

#pragma unroll
    for (int mt = 0; mt < 4; mt++) {
#pragma unroll
        for (int part = 0; part < 2; part++) {
            int co = mt * 16 + gid + part * 8;
            float v0 = part ? d0[mt][2] : d0[mt][0];
            float v1 = part ? d0[mt][3] : d0[mt][1];
            float v2 = part ? d1[mt][2] : d1[mt][0];
            float v3 = part ? d1[mt][3] : d1[mt][1];
            if (tig == 0) v0 -= s0s[co];
            if (tig == 1) v3 -= s2s[co];
            bool val2 = tig < 2;
            float s = v0 + v1 + (val2 ? v2 + v3 : 0.f);
            s += __shfl_xor_sync(0xffffffffu, s, 1);
            s += __shfl_xor_sync(0xffffffffu, s, 2);
            float mu = s * (1.0f / 12.0f);
            float e0 = v0 - mu, e1 = v1 - mu, e2 = v2 - mu, e3 = v3 - mu;
            float q = e0 * e0 + e1 * e1 + (val2 ? e2 * e2 + e3 * e3 : 0.f);
            q += __shfl_xor_sync(0xffffffffu, q, 1);
            q += __shfl_xor_sync(0xffffffffu, q, 2);
            float sc = rsqrtf(q * (1.0f / 12.0f) + 1e-5f) * gms[co];
            float bt = bes[co];
            float r = fmaxf(e0 * sc + bt, 0.f) + fmaxf(e1 * sc + bt, 0.f)
                    + (val2 ? fmaxf(e2 * sc + bt, 0.f) + fmaxf(e3 * sc + bt, 0.f) : 0.f);
            r += __shfl_xor_sync(0xffffffffu, r, 1);
            r += __shfl_xor_sync(0xffffffffu, r, 2);
            if (tig == 0) hbar[local * 64 + co] = r * (1.0f / 12.0f);
        }
    }
    __syncwarp();

    {
        const float4* hl4 = reinterpret_cast<const float4*>(hbar + local * 64);
        const float2* gp = reinterpret_cast<const float2*>(gw) + lane;
        u64 oacc = splat2(0.f);
        for (int c4 = 0; c4 < 16; c4++) {
            float4 hc = hl4[c4];
            int c = c4 * 4;
            float2 g0 = __ldg(gp + (c + 0) * 32);
            float2 g1 = __ldg(gp + (c + 1) * 32);
            float2 g2 = __ldg(gp + (c + 2) * 32);
            float2 g3 = __ldg(gp + (c + 3) * 32);
            fma2(oacc, splat2(hc.x), pack2(g0.x, g0.y));
            fma2(oacc, splat2(hc.y), pack2(g1.x, g1.y));
            fma2(oacc, splat2(hc.z), pack2(g2.x, g2.y));
            fma2(oacc, splat2(hc.w), pack2(g3.x, g3.y));
        }
        float2 o = unpack2(oacc);
        *reinterpret_cast<float2*>(g_xs2 + (size_t)n * 64 + 2 * lane) = o;
    }
}

// ---------------- layer 2 aggregation + output linear + scratch re-zero ----------------
__global__ void k_agg2_out(const float* __restrict__ gb, const float* __restrict__ ow,
                           const float* __restrict__ ob, float* __restrict__ out) {
    __shared__ float ows[64 * 32];
    __shared__ float am[8][64];
    int tid = threadIdx.x;
    for (int i = tid; i < 64 * 32; i += 256) ows[i] = ow[i];
    __syncthreads();
    int wslot = tid >> 5;
    int lane = tid & 31;
    int n = blockIdx.x * 8 + wslot;
    if (n >= NN) return;
    u64 h = __ldg(&g_hist[n]);
    int cnt = (int)(h >> 40);
    float deg = (float)(h & FIXM) * (1.0f / FIXP);
    float d2 = 1.0f / (deg + 1.0f);
    if (lane == 0) { g_hist[n] = 0ull; g_fill[n] = 0; }
    const int* csr = g_csrc + n * CAP;
    const float* cnm = g_cnorm + n * CAP;
    float a0 = 0.f, a1 = 0.f;
    int sN = 0; float wN = 0.f;
    if (cnt > 0) { sN = __ldg(csr); wN = __ldg(cnm); }
    for (int i = 0; i < cnt; i++) {
        int s = sN; float w = wN;
        if (i + 1 < cnt) { sN = __ldg(csr + i + 1); wN = __ldg(cnm + i + 1); }
        float2 f = __ldg(reinterpret_cast<const float2*>(g_xs2 + (size_t)s * 64) + lane);
        a0 += w * f.x;
        a1 += w * f.y;
    }
    float2 pn = *(reinterpret_cast<const float2*>(g_xs2 + (size_t)n * 64) + lane);
    float2 gb2v = *(reinterpret_cast<const float2*>(gb) + lane);
    a0 += d2 * pn.x + gb2v.x;
    a1 += d2 * pn.y + gb2v.y;
    am[wslot][2 * lane] = a0;
    am[wslot][2 * lane + 1] = a1;
    __syncwarp();
    float s = ob[lane];
    const float* amr = am[wslot];
#pragma unroll 8
    for (int c = 0; c < 64; c++) s += amr[c] * ows[c * 32 + lane];
    out[(size_t)n * 32 + lane] = s;
}

// ---------------- launch ----------------
extern "C" void kernel_launch(void* const* d_in, const int* in_sizes, int n_in,
                              void* d_out, int out_size) {
    const float* x    = (const float*)d_in[0];
    const int*   ei   = (const int*)d_in[1];
    const float* ew   = (const float*)d_in[2];
    const float* cw1  = (const float*)d_in[3];
    const float* ga1  = (const float*)d_in[5];
    const float* be1  = (const float*)d_in[6];
    const float* gw1  = (const float*)d_in[7];
    const float* gb1  = (const float*)d_in[8];
    const float* cw2  = (const float*)d_in[9];
    const float* ga2  = (const float*)d_in[11];
    const float* be2  = (const float*)d_in[12];
    const float* gw2  = (const float*)d_in[13];
    const float* gb2  = (const float*)d_in[14];
    const float* ow   = (const float*)d_in[15];
    const float* ob   = (const float*)d_in[16];
    float* out = (float*)d_out;

    const int smem1 = (128 + 64 * 52 + 8 * 14 * 20 + 8 * 12 * 32) * 4;    // ~34.3KB
    const int smem2 = (256 + 64 * 100 + L2N * 14 * 36 + L2N * 64) * 4;    // ~44.8KB
    static bool attr_set = false;
    if (!attr_set) {
        cudaFuncSetAttribute(k_l1scat, cudaFuncAttributeMaxDynamicSharedMemorySize, smem1);
        cudaFuncSetAttribute(k_l2fused, cudaFuncAttributeMaxDynamicSharedMemorySize, smem2);
        attr_set = true;
    }

    // 4 launches; k_agg2_out at profile slot 4
    k_histcompose<<<625 + 41, 256>>>(ei, ew, cw2, gw1, gb1, cw1);
    k_l1scat<<<1250 + 625, 256, smem1>>>(x, ga1, be1, ei, ew);
    k_l2fused<<<(NN + L2N - 1) / L2N, 32 * L2N, smem2>>>(ga2, be2, gw2);
    k_agg2_out<<<(NN + 7) / 8, 256>>>(gb2, ow, ob, out);
}

// round 17
// speedup vs baseline: 1.1967x; 1.1455x over previous
#include <cuda_runtime.h>
#include <cuda_fp16.h>
#include <cuda_bf16.h>
#include <cstdint>

#define TT 12
#define NN 10000
#define EE 160000
#define CAP 96   // padded CSR row capacity (deg ~ Poisson(16); P(>96) ~ 1e-40)

typedef unsigned long long u64;

__device__ __forceinline__ u64 splat2(float v) {
    u64 r; asm("mov.b64 %0,{%1,%1};" : "=l"(r) : "f"(v)); return r;
}
__device__ __forceinline__ u64 pack2(float lo, float hi) {
    u64 r; asm("mov.b64 %0,{%1,%2};" : "=l"(r) : "f"(lo), "f"(hi)); return r;
}
__device__ __forceinline__ void fma2(u64& acc, u64 a, u64 b) {
    asm("fma.rn.f32x2 %0,%1,%2,%0;" : "+l"(acc) : "l"(a), "l"(b));
}
__device__ __forceinline__ void add2(u64& acc, u64 v) {
    asm("add.rn.f32x2 %0,%0,%1;" : "+l"(acc) : "l"(v));
}
__device__ __forceinline__ float2 unpack2(u64 v) {
    float2 f; asm("mov.b64 {%0,%1},%2;" : "=f"(f.x), "=f"(f.y) : "l"(v)); return f;
}
__device__ __forceinline__ __half2 u2h2(unsigned int u) {
    return *reinterpret_cast<const __half2*>(&u);
}
__device__ __forceinline__ u64 h2u64(__half2 h) {
    float2 f = __half22float2(h);
    return pack2(f.x, f.y);
}

// ---------------- device scratch ----------------
__device__ __align__(16) __half g_h1h[NN * TT * 64];  // layer1 h, NODE-MAJOR [n][t][ch], 96 uint4/row
__device__ float   g_ys2[NN * 32];         // (mean_t h2 @ gw2) @ ow   [N,32]
__device__ __half  g_w1h[64 * 96];
__device__ __half  g_w2h[64 * 192];
__device__ float   g_gcomb[64 * 32];       // gw2 @ ow
__device__ float   g_gbow[32];             // gb2 @ ow + ob
__device__ float   g_S0[64];
__device__ float   g_S2[64];
__device__ u64     g_hist[NN];
__device__ int     g_fill[NN];
__device__ int     g_csrc[NN * CAP];
__device__ float   g_cnorm[NN * CAP];

#define FIXP 16777216.0f   // 2^24
#define FIXM 0xFFFFFFFFFFull
#define ROWQ 96            // uint4 per g_h1h node row

// ======== fused: edge histogram (blocks [0,625)) + weight prep (blocks [625,674)) ========
__global__ void k_histcompose(const int* __restrict__ ei, const float* __restrict__ ew,
                              const float* __restrict__ w2, const float* __restrict__ gw1,
                              const float* __restrict__ gb1, const float* __restrict__ w1,
                              const float* __restrict__ gw2, const float* __restrict__ ow,
                              const float* __restrict__ ob, const float* __restrict__ gb2) {
    if (blockIdx.x < 625) {
        int e = blockIdx.x * 256 + threadIdx.x;
        if (e >= EE) return;
        int d = ei[EE + e];
        u64 v = ((u64)1 << 40) | (u64)(ew[e] * FIXP);
        atomicAdd(&g_hist[d], v);
        return;
    }
    int idx = (blockIdx.x - 625) * 256 + threadIdx.x;
    if (idx < 4096) {
        int co = idx >> 6, c = idx & 63;
        const float* w2r = w2 + co * 192;
        const float* g1r = gw1 + c * 64;
        float s0 = 0.f, s1 = 0.f, s2 = 0.f;
        for (int d = 0; d < 64; d++) {
            float g = g1r[d];
            s0 += w2r[d * 3 + 0] * g;
            s1 += w2r[d * 3 + 1] * g;
            s2 += w2r[d * 3 + 2] * g;
        }
        g_w2h[co * 192 +   0 + c] = __float2half_rn(s0);
        g_w2h[co * 192 +  64 + c] = __float2half_rn(s1);
        g_w2h[co * 192 + 128 + c] = __float2half_rn(s2);
    } else if (idx < 4096 + 128) {
        int j = idx - 4096;
        int co = j & 63, which = j >> 6;
        const float* w2r = w2 + co * 192;
        float s = 0.f;
        int k = which ? 2 : 0;
        for (int d = 0; d < 64; d++) s += w2r[d * 3 + k] * gb1[d];
        if (which) g_S2[co] = s; else g_S0[co] = s;
    } else if (idx >= 4224 && idx < 10368) {
        int j = idx - 4224;
        int co = j / 96, rem = j % 96;
        int ci = rem / 3, k = rem % 3;
        g_w1h[co * 96 + k * 32 + ci] = __float2half_rn(w1[j]);
    } else if (idx >= 10368 && idx < 10368 + 2048) {
        int j = idx - 10368;           // gcomb[c][o] = sum_d gw2[c][d] * ow[d][o]
        int c = j >> 5, o = j & 31;
        const float* gr = gw2 + c * 64;
        float s = 0.f;
        for (int d = 0; d < 64; d++) s += gr[d] * ow[d * 32 + o];
        g_gcomb[c * 32 + o] = s;
    } else if (idx >= 12416 && idx < 12448) {
        int o = idx - 12416;           // gbow[o] = sum_d gb2[d] * ow[d][o] + ob[o]
        float s = ob[o];
        for (int d = 0; d < 64; d++) s += gb2[d] * ow[d * 32 + o];
        g_gbow[o] = s;
    }
}

// ======================= fused: layer 1 (MMA conv + IN + relu) + padded-CSR scatter ========
#define L1N 8
__global__ void __launch_bounds__(32 * L1N, 3)
k_l1scat(const float* __restrict__ x, const float* __restrict__ gamma,
         const float* __restrict__ beta, const int* __restrict__ ei,
         const float* __restrict__ ew) {
    if (blockIdx.x >= 1250) {
        int e = (blockIdx.x - 1250) * 256 + threadIdx.x;
        if (e >= EE) return;
        int srcn = ei[e];
        int d = ei[EE + e];
        u64 hs = __ldg(&g_hist[srcn]);
        u64 hd = __ldg(&g_hist[d]);
        float dis_s = rsqrtf((float)(hs & FIXM) * (1.0f / FIXP) + 1.0f);
        float dis_d = rsqrtf((float)(hd & FIXM) * (1.0f / FIXP) + 1.0f);
        int pos = atomicAdd(&g_fill[d], 1);
        int idx = d * CAP + pos;
        g_csrc[idx] = srcn;
        g_cnorm[idx] = dis_s * ew[e] * dis_d;
        return;
    }
    // ---- layer 1 ----
    extern __shared__ float sm[];
    float* gms = sm;
    float* bes = gms + 64;
    unsigned int* aw = reinterpret_cast<unsigned int*>(bes + 64);  // [64][52]
    unsigned int* xr = aw + 64 * 52;                               // L1N * 14*20
    __half* hst = reinterpret_cast<__half*>(xr + L1N * 14 * 20);   // L1N * 12*64

    int tid = threadIdx.x;
    const int NT = 32 * L1N;
    for (int i = tid; i < 64; i += NT) { gms[i] = gamma[i]; bes[i] = beta[i]; }
    const unsigned int* wsrc = reinterpret_cast<const unsigned int*>(g_w1h);
    for (int i = tid; i < 64 * 48; i += NT) {
        int co = i / 48, k2 = i % 48;
        aw[co * 52 + k2] = wsrc[i];
    }
    int local = tid >> 5;
    int lane = tid & 31;
    int gid = lane >> 2;
    int tig = lane & 3;
    int n = blockIdx.x * L1N + local;
    unsigned int* xrow = xr + local * (14 * 20);
    __half* hstage = hst + local * (12 * 64);

    {
        int pair = lane & 15;
        int th = lane >> 4;
        if (lane < 16) { xrow[0 * 20 + lane] = 0u; xrow[13 * 20 + lane] = 0u; }
#pragma unroll
        for (int tt = 0; tt < 6; tt++) {
            int t = th * 6 + tt;
            float2 f = __ldg(reinterpret_cast<const float2*>(x + ((size_t)t * NN + n) * 32) + pair);
            __half2 h = __floats2half2_rn(f.x, f.y);
            xrow[(t + 1) * 20 + pair] = *reinterpret_cast<unsigned int*>(&h);
        }
    }
    __syncthreads();

    float d0[4][4], d1[4][4];
#pragma unroll
    for (int m = 0; m < 4; m++)
#pragma unroll
        for (int r = 0; r < 4; r++) { d0[m][r] = 0.f; d1[m][r] = 0.f; }

#pragma unroll
    for (int kt = 0; kt < 6; kt++) {
        int tap = kt >> 1;
        int l0 = (kt & 1) * 8;
        int tp0 = gid + tap;
        int tp1 = gid + 8 + tap; if (tp1 > 13) tp1 = 13;
        unsigned int b00 = xrow[tp0 * 20 + l0 + tig];
        unsigned int b01 = xrow[tp0 * 20 + l0 + tig + 4];
        unsigned int b10 = xrow[tp1 * 20 + l0 + tig];
        unsigned int b11 = xrow[tp1 * 20 + l0 + tig + 4];
#pragma unroll
        for (int mt = 0; mt < 4; mt++) {
            const unsigned int* ap = aw + (mt * 16 + gid) * 52 + kt * 8 + tig;
            unsigned int a0 = ap[0];
            unsigned int a1 = ap[8 * 52];
            unsigned int a2 = ap[4];
            unsigned int a3 = ap[8 * 52 + 4];
            asm volatile("mma.sync.aligned.m16n8k16.row.col.f32.f16.f16.f32 "
                "{%0,%1,%2,%3}, {%4,%5,%6,%7}, {%8,%9}, {%0,%1,%2,%3};"
                : "+f"(d0[mt][0]), "+f"(d0[mt][1]), "+f"(d0[mt][2]), "+f"(d0[mt][3])
                : "r"(a0), "r"(a1), "r"(a2), "r"(a3), "r"(b00), "r"(b01));
            asm volatile("mma.sync.aligned.m16n8k16.row.col.f32.f16.f16.f32 "
                "{%0,%1,%2,%3}, {%4,%5,%6,%7}, {%8,%9}, {%0,%1,%2,%3};"
                : "+f"(d1[mt][0]), "+f"(d1[mt][1]), "+f"(d1[mt][2]), "+f"(d1[mt][3])
                : "r"(a0), "r"(a1), "r"(a2), "r"(a3), "r"(b10), "r"(b11));
        }
    }

#pragma unroll
    for (int mt = 0; mt < 4; mt++) {
#pragma unroll
        for (int part = 0; part < 2; part++) {
            int co = mt * 16 + gid + part * 8;
            float v0 = part ? d0[mt][2] : d0[mt][0];
            float v1 = part ? d0[mt][3] : d0[mt][1];
            float v2 = part ? d1[mt][2] : d1[mt][0];
            float v3 = part ? d1[mt][3] : d1[mt][1];
            bool val2 = tig < 2;
            float s = v0 + v1 + (val2 ? v2 + v3 : 0.f);
            s += __shfl_xor_sync(0xffffffffu, s, 1);
            s += __shfl_xor_sync(0xffffffffu, s, 2);
            float mu = s * (1.0f / 12.0f);
            float e0 = v0 - mu, e1 = v1 - mu, e2 = v2 - mu, e3 = v3 - mu;
            float q = e0 * e0 + e1 * e1 + (val2 ? e2 * e2 + e3 * e3 : 0.f);
            q += __shfl_xor_sync(0xffffffffu, q, 1);
            q += __shfl_xor_sync(0xffffffffu, q, 2);
            float sc = rsqrtf(q * (1.0f / 12.0f) + 1e-5f) * gms[co];
            float bt = bes[co];
            hstage[(2 * tig) * 64 + co]     = __float2half_rn(fmaxf(e0 * sc + bt, 0.f));
            hstage[(2 * tig + 1) * 64 + co] = __float2half_rn(fmaxf(e1 * sc + bt, 0.f));
            if (val2) {
                hstage[(8 + 2 * tig) * 64 + co] = __float2half_rn(fmaxf(e2 * sc + bt, 0.f));
                hstage[(9 + 2 * tig) * 64 + co] = __float2half_rn(fmaxf(e3 * sc + bt, 0.f));
            }
        }
    }
    __syncwarp();
    {
        const uint4* hsu4 = reinterpret_cast<const uint4*>(hstage);
        uint4* outp = reinterpret_cast<uint4*>(g_h1h) + (size_t)n * ROWQ;
#pragma unroll
        for (int j = 0; j < 3; j++) outp[j * 32 + lane] = hsu4[j * 32 + lane];
    }
}

// ======================= fused: GCN aggregation + layer2 MMA + epi (writes ys2 [N,32]) ====
#define L2N 8
__global__ void __launch_bounds__(32 * L2N, 3)
k_l2fused(const float* __restrict__ gamma, const float* __restrict__ beta) {
    extern __shared__ float sm[];
    float* gms = sm;
    float* bes = gms + 64;
    float* s0s = bes + 64;
    float* s2s = s0s + 64;
    unsigned int* aw = reinterpret_cast<unsigned int*>(s2s + 64);  // [64][100]
    unsigned int* xr = aw + 64 * 100;                              // L2N * 14*36
    float* hbar = reinterpret_cast<float*>(xr + L2N * 14 * 36);

    int tid = threadIdx.x;
    const int NT = 32 * L2N;
    for (int i = tid; i < 64; i += NT) {
        gms[i] = gamma[i]; bes[i] = beta[i]; s0s[i] = g_S0[i]; s2s[i] = g_S2[i];
    }
    const unsigned int* wsrc = reinterpret_cast<const unsigned int*>(g_w2h);
    for (int i = tid; i < 64 * 96; i += NT) {
        int co = i / 96, k2 = i % 96;
        aw[co * 100 + k2] = wsrc[i];
    }
    __syncthreads();

    int local = tid >> 5;
    int lane = tid & 31;
    int gid = lane >> 2;
    int tig = lane & 3;
    int n = blockIdx.x * L2N + local;
    unsigned int* xrow = xr + local * (14 * 36);

    // ---- in-warp gather: lane owns 3 16B chunks q = lane + 32k of the 1536B node row ----
    {
        u64 h = __ldg(&g_hist[n]);
        int cnt = (int)(h >> 40);
        float deg = (float)(h & FIXM) * (1.0f / FIXP);
        float dd2 = 1.0f / (deg + 1.0f);
        const uint4* hbase = reinterpret_cast<const uint4*>(g_h1h);
        const int q0 = lane, q1 = lane + 32, q2 = lane + 64;

        u64 acc[12];
#pragma unroll
        for (int j = 0; j < 12; j++) acc[j] = splat2(0.f);
        const __half2 z = __float2half2_rn(0.f);
        __half2 gacc[12];
#pragma unroll
        for (int j = 0; j < 12; j++) gacc[j] = z;

        const int* csr = g_csrc + n * CAP;
        const float* cnm = g_cnorm + n * CAP;
        float wN = 0.f;
        uint4 c0N = {0,0,0,0}, c1N = {0,0,0,0}, c2N = {0,0,0,0};
        if (cnt > 0) {
            int s0 = __ldg(csr); wN = __ldg(cnm);
            const uint4* p = hbase + (size_t)s0 * ROWQ;
            c0N = __ldg(p + q0); c1N = __ldg(p + q1); c2N = __ldg(p + q2);
        }
        for (int i = 0; i < cnt; i++) {
            uint4 c0 = c0N, c1 = c1N, c2 = c2N;
            float w = wN;
            if (i + 1 < cnt) {
                int s1 = __ldg(csr + i + 1); wN = __ldg(cnm + i + 1);
                const uint4* p = hbase + (size_t)s1 * ROWQ;
                c0N = __ldg(p + q0); c1N = __ldg(p + q1); c2N = __ldg(p + q2);
            }
            __half2 wh = __float2half2_rn(w);
            gacc[0] = __hfma2(u2h2(c0.x), wh, gacc[0]);
            gacc[1] = __hfma2(u2h2(c0.y), wh, gacc[1]);
            gacc[2] = __hfma2(u2h2(c0.z), wh, gacc[2]);
            gacc[3] = __hfma2(u2h2(c0.w), wh, gacc[3]);
            gacc[4] = __hfma2(u2h2(c1.x), wh, gacc[4]);
            gacc[5] = __hfma2(u2h2(c1.y), wh, gacc[5]);
            gacc[6] = __hfma2(u2h2(c1.z), wh, gacc[6]);
            gacc[7] = __hfma2(u2h2(c1.w), wh, gacc[7]);
            gacc[8] = __hfma2(u2h2(c2.x), wh, gacc[8]);
            gacc[9] = __hfma2(u2h2(c2.y), wh, gacc[9]);
            gacc[10] = __hfma2(u2h2(c2.z), wh, gacc[10]);
            gacc[11] = __hfma2(u2h2(c2.w), wh, gacc[11]);
            if ((i & 3) == 3) {
#pragma unroll
                for (int j = 0; j < 12; j++) { add2(acc[j], h2u64(gacc[j])); gacc[j] = z; }
            }
        }
#pragma unroll
        for (int j = 0; j < 12; j++) add2(acc[j], h2u64(gacc[j]));

        // self-loop term in f32
        {
            const uint4* pn = hbase + (size_t)n * ROWQ;
            uint4 s0 = __ldg(pn + q0), s1 = __ldg(pn + q1), s2 = __ldg(pn + q2);
            u64 D2 = splat2(dd2);
            fma2(acc[0], D2, h2u64(u2h2(s0.x)));
            fma2(acc[1], D2, h2u64(u2h2(s0.y)));
            fma2(acc[2], D2, h2u64(u2h2(s0.z)));
            fma2(acc[3], D2, h2u64(u2h2(s0.w)));
            fma2(acc[4], D2, h2u64(u2h2(s1.x)));
            fma2(acc[5], D2, h2u64(u2h2(s1.y)));
            fma2(acc[6], D2, h2u64(u2h2(s1.z)));
            fma2(acc[7], D2, h2u64(u2h2(s1.w)));
            fma2(acc[8], D2, h2u64(u2h2(s2.x)));
            fma2(acc[9], D2, h2u64(u2h2(s2.y)));
            fma2(acc[10], D2, h2u64(u2h2(s2.z)));
            fma2(acc[11], D2, h2u64(u2h2(s2.w)));
        }

        xrow[0 * 36 + lane] = 0u;
        xrow[13 * 36 + lane] = 0u;
#pragma unroll
        for (int k = 0; k < 3; k++) {
            int q = lane + 32 * k;
            int t = q >> 3;
            int col0 = (q & 7) * 4;
            uint4 o;
            float2 f;
            __half2 hv;
            f = unpack2(acc[4 * k + 0]); hv = __floats2half2_rn(f.x, f.y); o.x = *reinterpret_cast<unsigned int*>(&hv);
            f = unpack2(acc[4 * k + 1]); hv = __floats2half2_rn(f.x, f.y); o.y = *reinterpret_cast<unsigned int*>(&hv);
            f = unpack2(acc[4 * k + 2]); hv = __floats2half2_rn(f.x, f.y); o.z = *reinterpret_cast<unsigned int*>(&hv);
            f = unpack2(acc[4 * k + 3]); hv = __floats2half2_rn(f.x, f.y); o.w = *reinterpret_cast<unsigned int*>(&hv);
            *reinterpret_cast<uint4*>(xrow + (t + 1) * 36 + col0) = o;
        }
    }
    __syncwarp();

    float d0[4][4], d1[4][4];
#pragma unroll
    for (int m = 0; m < 4; m++)
#pragma unroll
        for (int r = 0; r < 4; r++) { d0[m][r] = 0.f; d1[m][r] = 0.f; }

#pragma unroll
    for (int kt = 0; kt < 12; kt++) {
        int tap = kt >> 2;
        int l0 = (kt & 3) * 8;
        int tp0 = gid + tap;
        int tp1 = gid + 8 + tap; if (tp1 > 13) tp1 = 13;
        unsigned int b00 = xrow[tp0 * 36 + l0 + tig];
        unsigned int b01 = xrow[tp0 * 36 + l0 + tig + 4];
        unsigned int b10 = xrow[tp1 * 36 + l0 + tig];
        unsigned int b11 = xrow[tp1 * 36 + l0 + tig + 4];
#pragma unroll
        for (int mt = 0; mt < 4; mt++) {
            const unsigned int* ap = aw + (mt * 16 + gid) * 100 + kt * 8 + tig;
            unsigned int a0 = ap[0];
            unsigned int a1 = ap[8 * 100];
            unsigned int a2 = ap[4];
            unsigned int a3 = ap[8 * 100 + 4];
            asm volatile("mma.sync.aligned.m16n8k16.row.col.f32.f16.f16.f32 "
                "{%0,%1,%2,%3}, {%4,%5,%6,%7}, {%8,%9}, {%0,%1,%2,%3};"
                : "+f"(d0[mt][0]), "+f"(d0[mt][1]), "+f"(d0[mt][2]), "+f"(d0[mt][3])
                : "r"(a0), "r"(a1), "r"(a2), "r"(a3), "r"(b00), "r"(b01));
            asm volatile("mma.sync.aligned.m16n8k16.row.col.f32.f16.f16.f32 "
                "{%0,%1,%2,%3}, {%4,%5,%6,%7}, {%8,%9}, {%0,%1,%2,%3};"
                : "+f"(d1[mt][0]), "+f"(d1[mt][1]), "+f"(d1[mt][2]), "+f"(d1[mt][3])
                : "r"(a0), "r"(a1), "r"(a2), "r"(a3), "r"(b10), "r"(b11));
        }
    }

#pragma unroll
    for (int mt = 0; mt < 4; mt++) {
#pragma unroll
        for (int part = 0; part < 2; part++) {
            int co = mt * 16 + gid + part * 8;
            float v0 = part ? d0[mt][2] : d0[mt][0];
            float v1 = part ? d0[mt][3] : d0[mt][1];
            float v2 = part ? d1[mt][2] : d1[mt][0];
            float v3 = part ? d1[mt][3] : d1[mt][1];
            if (tig == 0) v0 -= s0s[co];
            if (tig == 1) v3 -= s2s[co];
            bool val2 = tig < 2;
            float s = v0 + v1 + (val2 ? v2 + v3 : 0.f);
            s += __shfl_xor_sync(0xffffffffu, s, 1);
            s += __shfl_xor_sync(0xffffffffu, s, 2);
            float mu = s * (1.0f / 12.0f);
            float e0 = v0 - mu, e1 = v1 - mu, e2 = v2 - mu, e3 = v3 - mu;
            float q = e0 * e0 + e1 * e1 + (val2 ? e2 * e2 + e3 * e3 : 0.f);
            q += __shfl_xor_sync(0xffffffffu, q, 1);
            q += __shfl_xor_sync(0xffffffffu, q, 2);
            float sc = rsqrtf(q * (1.0f / 12.0f) + 1e-5f) * gms[co];
            float bt = bes[co];
            float r = fmaxf(e0 * sc + bt, 0.f) + fmaxf(e1 * sc + bt, 0.f)
                    + (val2 ? fmaxf(e2 * sc + bt, 0.f) + fmaxf(e3 * sc + bt, 0.f) : 0.f);
            r += __shfl_xor_sync(0xffffffffu, r, 1);
            r += __shfl_xor_sync(0xffffffffu, r, 2);
            if (tig == 0) hbar[local * 64 + co] = r * (1.0f / 12.0f);
        }
    }
    __syncwarp();

    // ys2[n][lane] = sum_c hbar[c] * gcomb[c][lane]
    {
        const float4* hl4 = reinterpret_cast<const float4*>(hbar + local * 64);
        const float* gc = g_gcomb + lane;
        float s = 0.f;
        for (int c4 = 0; c4 < 16; c4++) {
            float4 hc = hl4[c4];
            int c = c4 * 4;
            s += hc.x * __ldg(gc + (c + 0) * 32);
            s += hc.y * __ldg(gc + (c + 1) * 32);
            s += hc.z * __ldg(gc + (c + 2) * 32);
            s += hc.w * __ldg(gc + (c + 3) * 32);
        }
        g_ys2[(size_t)n * 32 + lane] = s;
    }
}

// ---------------- final aggregation over ys2 + bias + scratch re-zero ----------------
__global__ void k_agg2_out(float* __restrict__ out) {
    int tid = threadIdx.x;
    int wslot = tid >> 5;
    int lane = tid & 31;
    int n = blockIdx.x * 8 + wslot;
    if (n >= NN) return;
    u64 h = __ldg(&g_hist[n]);
    int cnt = (int)(h >> 40);
    float deg = (float)(h & FIXM) * (1.0f / FIXP);
    float d2 = 1.0f / (deg + 1.0f);
    if (lane == 0) { g_hist[n] = 0ull; g_fill[n] = 0; }
    const int* csr = g_csrc + n * CAP;
    const float* cnm = g_cnorm + n * CAP;
    float a = 0.f;
    int sN = 0; float wN = 0.f;
    if (cnt > 0) { sN = __ldg(csr); wN = __ldg(cnm); }
    for (int i = 0; i < cnt; i++) {
        int s = sN; float w = wN;
        if (i + 1 < cnt) { sN = __ldg(csr + i + 1); wN = __ldg(cnm + i + 1); }
        a += w * __ldg(g_ys2 + (size_t)s * 32 + lane);
    }
    a += d2 * g_ys2[(size_t)n * 32 + lane] + g_gbow[lane];
    out[(size_t)n * 32 + lane] = a;
}

// ---------------- launch ----------------
extern "C" void kernel_launch(void* const* d_in, const int* in_sizes, int n_in,
                              void* d_out, int out_size) {
    const float* x    = (const float*)d_in[0];
    const int*   ei   = (const int*)d_in[1];
    const float* ew   = (const float*)d_in[2];
    const float* cw1  = (const float*)d_in[3];
    const float* ga1  = (const float*)d_in[5];
    const float* be1  = (const float*)d_in[6];
    const float* gw1  = (const float*)d_in[7];
    const float* gb1  = (const float*)d_in[8];
    const float* cw2  = (const float*)d_in[9];
    const float* ga2  = (const float*)d_in[11];
    const float* be2  = (const float*)d_in[12];
    const float* gw2  = (const float*)d_in[13];
    const float* gb2  = (const float*)d_in[14];
    const float* ow   = (const float*)d_in[15];
    const float* ob   = (const float*)d_in[16];
    float* out = (float*)d_out;

    const int smem1 = (128 + 64 * 52 + 8 * 14 * 20 + 8 * 12 * 32) * 4;    // ~34.3KB
    const int smem2 = (256 + 64 * 100 + L2N * 14 * 36 + L2N * 64) * 4;    // ~44.8KB
    static bool attr_set = false;
    if (!attr_set) {
        cudaFuncSetAttribute(k_l1scat, cudaFuncAttributeMaxDynamicSharedMemorySize, smem1);
        cudaFuncSetAttribute(k_l2fused, cudaFuncAttributeMaxDynamicSharedMemorySize, smem2);
        attr_set = true;
    }

    // 4 launches; k_agg2_out at profile slot 4
    k_histcompose<<<625 + 49, 256>>>(ei, ew, cw2, gw1, gb1, cw1, gw2, ow, ob, gb2);
    k_l1scat<<<1250 + 625, 256, smem1>>>(x, ga1, be1, ei, ew);
    k_l2fused<<<(NN + L2N - 1) / L2N, 32 * L2N, smem2>>>(ga2, be2);
    k_agg2_out<<<(NN + 7) / 8, 256>>>(out);
}